// round 14
// baseline (speedup 1.0000x reference)
#include <cuda_runtime.h>
#include <cuda_fp16.h>
#include <cstdint>

#define BV   16
#define TV   2048
#define INV  80
#define HV   512
#define DV   512
#define KV   1024
#define ROWS (BV * TV)   // 32768

typedef unsigned long long ull;

// ---------------- scratch (device globals; no allocation allowed) ----------
__device__ __half g_mh[(size_t)ROWS * INV];
__device__ __half g_ml[(size_t)ROWS * INV];
__device__ __half g_xh[(size_t)ROWS * DV];
__device__ __half g_xl[(size_t)ROWS * DV];
__device__ __half g_yh[(size_t)ROWS * DV];
__device__ __half g_yl[(size_t)ROWS * DV];
#define OW1 0
#define OW2 131072
#define OW3 917504
#define OW4 1703936
#define WTOT (1826816 + 128 * 1536)   // pad: dec2 N-tail clamp stays in-bounds
__device__ __half g_wh[WTOT];
__device__ __half g_wl[WTOT];
__device__ __half g_cbh[(size_t)KV * DV];
__device__ float  g_cn[KV];
__device__ float4 g_part[(size_t)ROWS * 4];
__device__ ull    g_keys[ROWS];
__device__ int    g_list[ROWS];
__device__ int    g_cnt[1];
__device__ float  g_idxd[ROWS];

// ---------------- helpers --------------------------------------------------
__device__ __forceinline__ uint32_t smem_u32(const void* p) {
    uint32_t a;
    asm("{ .reg .u64 t; cvta.to.shared.u64 t, %1; cvt.u32.u64 %0, t; }"
        : "=r"(a) : "l"(p));
    return a;
}
__device__ __forceinline__ void ldsm4(uint32_t* r, uint32_t addr) {
    asm volatile("ldmatrix.sync.aligned.m8n8.x4.shared.b16 {%0,%1,%2,%3}, [%4];"
                 : "=r"(r[0]), "=r"(r[1]), "=r"(r[2]), "=r"(r[3]) : "r"(addr));
}
__device__ __forceinline__ void mma16816(float* c, const uint32_t* a, const uint32_t* b) {
    asm volatile(
        "mma.sync.aligned.m16n8k16.row.col.f32.f16.f16.f32 "
        "{%0,%1,%2,%3}, {%4,%5,%6,%7}, {%8,%9}, {%0,%1,%2,%3};"
        : "+f"(c[0]), "+f"(c[1]), "+f"(c[2]), "+f"(c[3])
        : "r"(a[0]), "r"(a[1]), "r"(a[2]), "r"(a[3]), "r"(b[0]), "r"(b[1]));
}
__device__ __forceinline__ void cp16(uint32_t dst, const void* src, uint32_t sz) {
    asm volatile("cp.async.cg.shared.global [%0], [%1], 16, %2;"
                 :: "r"(dst), "l"(src), "r"(sz));
}
#define CP_COMMIT() asm volatile("cp.async.commit_group;" ::: "memory")
#define CP_WAIT1()  asm volatile("cp.async.wait_group 1;" ::: "memory")

__device__ __forceinline__ unsigned ford(float f) {
    unsigned u = __float_as_uint(f);
    return (u & 0x80000000u) ? ~u : (u | 0x80000000u);
}
__device__ __forceinline__ void h_split(float v, __half& h, __half& l) {
    h = __float2half_rn(v);
    l = __float2half_rn(v - __half2float(h));
}

// ---------------- prep kernels ---------------------------------------------
__global__ void split_arr(const float* __restrict__ x, __half* __restrict__ h,
                          __half* __restrict__ l, size_t n) {
    size_t i = (size_t)blockIdx.x * blockDim.x + threadIdx.x;
    if (i < n) { __half hh, ll; h_split(x[i], hh, ll); h[i] = hh; l[i] = ll; }
}
__global__ void conv_h(const float* __restrict__ x, __half* __restrict__ h, size_t n) {
    size_t i = (size_t)blockIdx.x * blockDim.x + threadIdx.x;
    if (i < n) h[i] = __float2half_rn(x[i]);
}
template<int CIN, int COUT, int KTP>
__global__ void prep_w(const float* __restrict__ w, __half* __restrict__ wh,
                       __half* __restrict__ wl) {
    int i = blockIdx.x * 256 + threadIdx.x;
    if (i >= COUT * KTP) return;
    int co = i / KTP, k = i - co * KTP;
    float v = 0.f;
    if (k < 3 * CIN) {
        int d = k / CIN, ci = k - d * CIN;
        v = w[((size_t)co * CIN + ci) * 3 + d];
    }
    __half hh, ll; h_split(v, hh, ll);
    wh[i] = hh; wl[i] = ll;
}
__global__ void cnorm_init(const float* __restrict__ cb, float* __restrict__ cn,
                           int* __restrict__ cnt) {
    int k = blockIdx.x * 8 + (threadIdx.x >> 5);
    int lane = threadIdx.x & 31;
    float s = 0.f;
    const float* row = cb + (size_t)k * DV;
    for (int c = lane; c < DV; c += 32) { float v = row[c]; s += v * v; }
    #pragma unroll
    for (int o = 16; o; o >>= 1) s += __shfl_xor_sync(0xFFFFFFFFu, s, o);
    if (lane == 0) cn[k] = s;
    if (blockIdx.x == 0 && threadIdx.x == 0) cnt[0] = 0;
}
__global__ void gather_q(const ull* __restrict__ keys, const __half* __restrict__ cbh,
                         __half* __restrict__ qh, float* __restrict__ idxf) {
    int r0 = blockIdx.x * 128;
    int tid = threadIdx.x;
    if (tid < 128)
        idxf[r0 + tid] = (float)(unsigned)(keys[r0 + tid] & 0xFFFFFFFFu);
    for (int e = tid; e < 128 * DV; e += 256) {
        int r = e >> 9, c = e & 511;
        unsigned k = (unsigned)(keys[r0 + r] & 0xFFFFFFFFu);
        qh[(size_t)(r0 + r) * DV + c] = cbh[(size_t)k * DV + c];
    }
}

// ---------------- mma.sync fp16-split GEMM, 3-stage cp.async ----------------
// CTA tile 128 x NTILE. C[m,n] = sum_k A[m,k]*B[n,k]; optional im2col.
// PASSES=3: A0B1 + A0B0 + A1B0 (fp32-accurate split).
// EPI: 0 = bias(+relu) -> split fp16 hi/lo   1 = bias(+relu) -> fp16 hi only
//      2 = bias -> fp32 out (col<NB guard)
//      3 = VQ partials: per-row (min1, k1, min2) over this CTA's NTILE codes,
//          written to part[row*4 + blockIdx.x] (no atomics; aux = ||c||^2)
template<int CIN, int NB, int KT, int CONV, int PASSES, int EPI, int RELU,
         int OSTR, int NTILE>
__global__ __launch_bounds__(256, 1)
void mma_gemm(const __half* __restrict__ Ah, const __half* __restrict__ Al,
              const __half* __restrict__ Bh, const __half* __restrict__ Bl,
              const float* __restrict__ aux,
              __half* __restrict__ oh, __half* __restrict__ ol,
              float* __restrict__ of, float4* __restrict__ part)
{
    constexpr int NCH    = (KT + 31) / 32;
    constexpr int KTP    = NCH * 32;
    constexpr int LDS    = 40;
    constexpr int ATILEB = 128 * LDS * 2;
    constexpr int BTILEB = NTILE * LDS * 2;
    constexpr int STB    = (PASSES == 3) ? 2 * (ATILEB + BTILEB) : (ATILEB + BTILEB);
    constexpr int S      = 3;
    constexpr int WNF    = NTILE / 64;
    constexpr int NF     = 2 * WNF;

    extern __shared__ char smem[];
    const uint32_t sb = smem_u32(smem);

    const int tid = threadIdx.x, lane = tid & 31, wid = tid >> 5;
    const int warp_m = (wid & 1) * 64;
    const int warp_n = (wid >> 1) * (16 * WNF);
    const int n0 = blockIdx.x * NTILE, m0 = blockIdx.y * 128;
    const int bb = CONV ? m0 / TV : 0;
    const int tl = CONV ? m0 % TV : 0;

    float C[4][NF][4];
    #pragma unroll
    for (int i = 0; i < 4; i++)
        #pragma unroll
        for (int j = 0; j < NF; j++)
            #pragma unroll
            for (int q = 0; q < 4; q++) C[i][j][q] = 0.f;

    uint32_t aoff[4], boff[WNF];
    #pragma unroll
    for (int mi = 0; mi < 4; mi++)
        aoff[mi] = ((warp_m + mi * 16 + (lane & 15)) * LDS + (lane >> 4) * 8) * 2;
    #pragma unroll
    for (int bj = 0; bj < WNF; bj++)
        boff[bj] = ((warp_n + bj * 16 + ((lane >> 4) << 3) + (lane & 7)) * LDS
                    + ((lane >> 3) & 1) * 8) * 2;

    auto LOADC = [&](int cc, int st) {
        const uint32_t base = sb + (uint32_t)st * STB;
        #pragma unroll
        for (int p = 0; p < 2; p++) {
            int i_ = tid + p * 256;
            int r_ = i_ >> 2, v8 = (i_ & 3) * 8;
            uint32_t doff = (uint32_t)(r_ * LDS + v8) * 2;
            int k_ = cc * 32 + v8;
            int d_  = CONV ? k_ / CIN : 0;
            int ci_ = k_ - d_ * CIN;
            bool ok = (KT == KTP) || (k_ < KT);
            size_t row_;
            if (CONV) {
                int t_ = tl + r_ + d_ - 1;
                bool tin = (t_ >= 0 && t_ < TV);
                ok = ok && tin;
                row_ = (size_t)bb * TV + (tin ? t_ : 0);
            } else {
                row_ = (size_t)(m0 + r_);
            }
            if (!ok) ci_ = 0;
            uint32_t sz = ok ? 16u : 0u;
            const size_t go = row_ * CIN + ci_;
            cp16(base + doff, Ah + go, sz);
            if (PASSES == 3) cp16(base + ATILEB + doff, Al + go, sz);
        }
        const uint32_t bbase = base + (PASSES == 3 ? 2 : 1) * ATILEB;
        #pragma unroll
        for (int p = 0; p < NTILE / 64; p++) {
            int i_ = tid + p * 256;
            int r_ = i_ >> 2, v8 = (i_ & 3) * 8;
            uint32_t doff = (uint32_t)(r_ * LDS + v8) * 2;
            int k_ = cc * 32 + v8;
            bool ok = ((NB % NTILE) == 0) || ((n0 + r_) < NB);
            int rb = ok ? (n0 + r_) : 0;
            uint32_t sz = ok ? 16u : 0u;
            const size_t go = (size_t)rb * KTP + k_;
            cp16(bbase + doff, Bh + go, sz);
            if (PASSES == 3) cp16(bbase + BTILEB + doff, Bl + go, sz);
        }
    };

#define MMASET() do {                                                          \
    _Pragma("unroll")                                                          \
    for (int mi = 0; mi < 4; mi++)                                             \
        _Pragma("unroll")                                                      \
        for (int bj = 0; bj < WNF; bj++) {                                     \
            mma16816(C[mi][bj * 2],     Af[mi], &Bf[bj][0]);                   \
            mma16816(C[mi][bj * 2 + 1], Af[mi], &Bf[bj][2]);                   \
        } } while (0)

    LOADC(0, 0); CP_COMMIT();
    LOADC(1, 1); CP_COMMIT();

    for (int c = 0; c < NCH; c++) {
        CP_WAIT1();
        __syncthreads();
        const int st = c % S;
        const uint32_t a0b = sb + (uint32_t)st * STB;
        const uint32_t a1b = a0b + ATILEB;
        const uint32_t b0b = a0b + (PASSES == 3 ? 2 : 1) * ATILEB;
        const uint32_t b1b = b0b + BTILEB;

        #pragma unroll
        for (int ks = 0; ks < 2; ks++) {
            uint32_t Af[4][4], Bf[WNF][4];
            const uint32_t ko = ks * 32;
            if (PASSES == 3) {
                #pragma unroll
                for (int mi = 0; mi < 4; mi++) ldsm4(Af[mi], a0b + aoff[mi] + ko);
                #pragma unroll
                for (int bj = 0; bj < WNF; bj++) ldsm4(Bf[bj], b1b + boff[bj] + ko);
                MMASET();
                #pragma unroll
                for (int bj = 0; bj < WNF; bj++) ldsm4(Bf[bj], b0b + boff[bj] + ko);
                MMASET();
                #pragma unroll
                for (int mi = 0; mi < 4; mi++) ldsm4(Af[mi], a1b + aoff[mi] + ko);
                MMASET();
            } else {
                #pragma unroll
                for (int mi = 0; mi < 4; mi++) ldsm4(Af[mi], a0b + aoff[mi] + ko);
                #pragma unroll
                for (int bj = 0; bj < WNF; bj++) ldsm4(Bf[bj], b0b + boff[bj] + ko);
                MMASET();
            }
        }
        const int nc = c + S - 1;
        if (nc < NCH) LOADC(nc, nc % S);
        CP_COMMIT();
    }

    const int gid = lane >> 2, tig = lane & 3;

    if (EPI <= 2) {
        #pragma unroll
        for (int fi = 0; fi < NF; fi++) {
            int cg = n0 + warp_n + fi * 8 + 2 * tig;
            bool c0ok = (EPI != 2) || (cg < NB);
            bool c1ok = (EPI != 2) || (cg + 1 < NB);
            float bv0 = c0ok ? aux[cg] : 0.f;
            float bv1 = c1ok ? aux[cg + 1] : 0.f;
            #pragma unroll
            for (int mi = 0; mi < 4; mi++) {
                int r0 = m0 + warp_m + mi * 16 + gid;
                float v00 = C[mi][fi][0] + bv0, v01 = C[mi][fi][1] + bv1;
                float v10 = C[mi][fi][2] + bv0, v11 = C[mi][fi][3] + bv1;
                if (RELU) {
                    v00 = fmaxf(v00, 0.f); v01 = fmaxf(v01, 0.f);
                    v10 = fmaxf(v10, 0.f); v11 = fmaxf(v11, 0.f);
                }
                if (EPI == 2) {
                    if (c0ok) { of[(size_t)r0 * OSTR + cg] = v00;
                                of[(size_t)(r0 + 8) * OSTR + cg] = v10; }
                    if (c1ok) { of[(size_t)r0 * OSTR + cg + 1] = v01;
                                of[(size_t)(r0 + 8) * OSTR + cg + 1] = v11; }
                } else {
                    __half h00, h01, h10, h11, l00, l01, l10, l11;
                    h_split(v00, h00, l00); h_split(v01, h01, l01);
                    h_split(v10, h10, l10); h_split(v11, h11, l11);
                    *(__half2*)(oh + (size_t)r0 * OSTR + cg)       = __halves2half2(h00, h01);
                    *(__half2*)(oh + (size_t)(r0 + 8) * OSTR + cg) = __halves2half2(h10, h11);
                    if (EPI == 0) {
                        *(__half2*)(ol + (size_t)r0 * OSTR + cg)       = __halves2half2(l00, l01);
                        *(__half2*)(ol + (size_t)(r0 + 8) * OSTR + cg) = __halves2half2(l10, l11);
                    }
                }
            }
        }
    } else {
        // EPI == 3: per-CTA (min1, k1, min2) partials, no atomics.
        // redm lives in stage-1 smem (chunk NCH-2's reads completed at the
        // final loop-top __syncthreads; no cp.async targets it afterwards).
        const int wn = wid >> 1;
        float4* redm = (float4*)(smem + STB);
        #pragma unroll
        for (int mi = 0; mi < 4; mi++) {
            #pragma unroll
            for (int h = 0; h < 2; h++) {
                float c1 = 3.4e38f, c2 = 3.4e38f; int k1 = 0;
                #pragma unroll
                for (int fi = 0; fi < NF; fi++) {
                    int cg = n0 + warp_n + fi * 8 + 2 * tig;
                    float d0 = aux[cg]     - 2.f * C[mi][fi][2 * h];
                    float d1 = aux[cg + 1] - 2.f * C[mi][fi][2 * h + 1];
                    if (d0 < c1) { c2 = c1; c1 = d0; k1 = cg; }
                    else if (d0 < c2) c2 = d0;
                    if (d1 < c1) { c2 = c1; c1 = d1; k1 = cg + 1; }
                    else if (d1 < c2) c2 = d1;
                }
                #pragma unroll
                for (int o = 1; o <= 2; o <<= 1) {
                    float o1 = __shfl_xor_sync(0xFFFFFFFFu, c1, o);
                    float o2 = __shfl_xor_sync(0xFFFFFFFFu, c2, o);
                    int   ok = __shfl_xor_sync(0xFFFFFFFFu, k1, o);
                    if (o1 < c1 || (o1 == c1 && ok < k1)) {
                        c2 = fminf(c1, o2); c1 = o1; k1 = ok;
                    } else {
                        c2 = fminf(c2, o1);
                    }
                }
                if (tig == 0) {
                    int rl = warp_m + mi * 16 + h * 8 + gid;
                    redm[rl * 4 + wn] = make_float4(c1, __int_as_float(k1), c2, 0.f);
                }
            }
        }
        __syncthreads();
        if (tid < 128) {
            float m1 = 3.4e38f, m2 = 3.4e38f; int k1 = 0;
            #pragma unroll
            for (int w = 0; w < 4; w++) {
                float4 e = redm[tid * 4 + w];
                int ek = __float_as_int(e.y);
                if (e.x < m1 || (e.x == m1 && ek < k1)) {
                    m2 = fminf(m1, e.z); m1 = e.x; k1 = ek;
                } else {
                    m2 = fminf(m2, e.x);
                }
            }
            part[(size_t)(m0 + tid) * 4 + blockIdx.x] =
                make_float4(m1, __int_as_float(k1), m2, 0.f);
        }
    }
#undef MMASET
}

// ---------------- VQ merge: exact min1/min2 across the 4 N-block partials ---
__global__ __launch_bounds__(256)
void vq_merge(const float4* __restrict__ part, const __half* __restrict__ yh,
              ull* __restrict__ keys, int* __restrict__ list,
              int* __restrict__ cnt)
{
    const int w = threadIdx.x >> 5, lane = threadIdx.x & 31;
    const int row = blockIdx.x * 8 + w;
    const uint4* zp = (const uint4*)(yh + (size_t)row * DV);
    float zsq = 0.f;
    #pragma unroll
    for (int it = 0; it < 2; it++) {
        uint4 v = zp[lane + it * 32];
        const __half2* hp = (const __half2*)&v;
        #pragma unroll
        for (int j = 0; j < 4; j++) {
            float2 f = __half22float2(hp[j]);
            zsq += f.x * f.x + f.y * f.y;
        }
    }
    #pragma unroll
    for (int o = 16; o; o >>= 1) zsq += __shfl_xor_sync(0xFFFFFFFFu, zsq, o);
    if (lane == 0) {
        float m1 = 3.4e38f, m2 = 3.4e38f; int k1 = 0;
        #pragma unroll
        for (int b = 0; b < 4; b++) {
            float4 e = part[(size_t)row * 4 + b];
            int ek = __float_as_int(e.y);
            if (e.x < m1 || (e.x == m1 && ek < k1)) {
                m2 = fminf(m1, e.z); m1 = e.x; k1 = ek;
            } else {
                m2 = fminf(m2, e.x);
            }
        }
        keys[row] = (((ull)ford(m1)) << 32) | (ull)(unsigned)k1;
        float eps = 0.05f * sqrtf(zsq) + 1e-2f;
        if (m2 - m1 < eps) {
            int p = atomicAdd(cnt, 1);
            list[p] = row;
        }
    }
}

// ---------------- VQ stage 2: exact fp32 re-rank for flagged rows -----------
__global__ __launch_bounds__(256)
void vq_exact(const int* __restrict__ list, const int* __restrict__ cnt,
              const __half* __restrict__ yh, const __half* __restrict__ yl,
              const float* __restrict__ cb, const float* __restrict__ cn,
              ull* __restrict__ keys)
{
    __shared__ __align__(16) float zs[16][516];
    __shared__ ull skeys[16];
    const int count = cnt[0];
    const int tid = threadIdx.x;

    for (int b0 = blockIdx.x * 16; b0 < count; b0 += gridDim.x * 16) {
        int nb = min(16, count - b0);
        __syncthreads();
        if (tid < 16) skeys[tid] = ~0ULL;
        for (int e = tid; e < nb * 512; e += 256) {
            int r = e >> 9, i = e & 511;
            size_t ro = (size_t)list[b0 + r] * DV + i;
            zs[r][i] = __half2float(yh[ro]) + __half2float(yl[ro]);
        }
        __syncthreads();
        for (int cc = 0; cc < 4; cc++) {
            int code = tid + cc * 256;
            const float4* cr = (const float4*)(cb + (size_t)code * DV);
            float acc[16];
            #pragma unroll
            for (int r = 0; r < 16; r++) acc[r] = 0.f;
            for (int i4 = 0; i4 < 128; i4++) {
                float4 wv = cr[i4];
                #pragma unroll
                for (int r = 0; r < 16; r++) {
                    float4 zv = *(const float4*)&zs[r][i4 * 4];
                    acc[r] += zv.x * wv.x + zv.y * wv.y + zv.z * wv.z + zv.w * wv.w;
                }
            }
            float c2v = cn[code];
            for (int r = 0; r < nb; r++) {
                float d = c2v - 2.f * acc[r];
                atomicMin(&skeys[r], (((ull)ford(d)) << 32) | (ull)(unsigned)code);
            }
        }
        __syncthreads();
        if (tid < nb) keys[list[b0 + tid]] = skeys[tid];
    }
}

// ---------------- launch ----------------------------------------------------
extern "C" void kernel_launch(void* const* d_in, const int* in_sizes, int n_in,
                              void* d_out, int out_size)
{
    const float* mels = (const float*)d_in[0];
    const float* ew1  = (const float*)d_in[1];
    const float* eb1  = (const float*)d_in[2];
    const float* ew2  = (const float*)d_in[3];
    const float* eb2  = (const float*)d_in[4];
    const float* cb   = (const float*)d_in[5];
    const float* dw1  = (const float*)d_in[6];
    const float* db1  = (const float*)d_in[7];
    const float* dw2  = (const float*)d_in[8];
    const float* db2  = (const float*)d_in[9];

    float* out = (float*)d_out;

    __half *mh, *ml, *xh, *xl, *yh, *yl, *wh, *wl, *cbh;
    float *cn, *idxd;
    float4 *partp;
    ull *keys;
    int *list, *cnt;
    cudaGetSymbolAddress((void**)&mh, g_mh);   cudaGetSymbolAddress((void**)&ml, g_ml);
    cudaGetSymbolAddress((void**)&xh, g_xh);   cudaGetSymbolAddress((void**)&xl, g_xl);
    cudaGetSymbolAddress((void**)&yh, g_yh);   cudaGetSymbolAddress((void**)&yl, g_yl);
    cudaGetSymbolAddress((void**)&wh, g_wh);   cudaGetSymbolAddress((void**)&wl, g_wl);
    cudaGetSymbolAddress((void**)&cbh, g_cbh);
    cudaGetSymbolAddress((void**)&cn, g_cn);
    cudaGetSymbolAddress((void**)&partp, g_part);
    cudaGetSymbolAddress((void**)&keys, g_keys);
    cudaGetSymbolAddress((void**)&list, g_list);
    cudaGetSymbolAddress((void**)&cnt, g_cnt);
    cudaGetSymbolAddress((void**)&idxd, g_idxd);

    float* recon = out;
    float* idx_f = (out_size >= (int)((size_t)ROWS * INV + ROWS))
                     ? out + (size_t)ROWS * INV
                     : idxd;

    constexpr int SM3_256 = 3 * 61440;   // 184320
    constexpr int SM1_256 = 3 * 30720;   //  92160
    constexpr int SM1_128 = 3 * 20480;   //  61440
    static bool attr_done = false;
    if (!attr_done) {
        cudaFuncSetAttribute(mma_gemm<INV, HV, 240, 1, 3, 0, 1, HV, 256>,
                             cudaFuncAttributeMaxDynamicSharedMemorySize, SM3_256);
        cudaFuncSetAttribute(mma_gemm<HV, DV, 1536, 1, 3, 0, 0, DV, 256>,
                             cudaFuncAttributeMaxDynamicSharedMemorySize, SM3_256);
        cudaFuncSetAttribute(mma_gemm<DV, KV, 512, 0, 1, 3, 0, 0, 256>,
                             cudaFuncAttributeMaxDynamicSharedMemorySize, SM1_256);
        cudaFuncSetAttribute(mma_gemm<DV, HV, 1536, 1, 1, 1, 1, HV, 256>,
                             cudaFuncAttributeMaxDynamicSharedMemorySize, SM1_256);
        cudaFuncSetAttribute(mma_gemm<HV, INV, 1536, 1, 1, 2, 0, INV, 128>,
                             cudaFuncAttributeMaxDynamicSharedMemorySize, SM1_128);
        attr_done = true;
    }

    // ---- prep ----
    {
        size_t n = (size_t)ROWS * INV;
        split_arr<<<(unsigned)((n + 255) / 256), 256>>>(mels, mh, ml, n);
    }
    prep_w<INV, HV, 256  ><<<(HV * 256  + 255) / 256, 256>>>(ew1, wh + OW1, wl + OW1);
    prep_w<HV,  DV, 1536 ><<<(DV * 1536 + 255) / 256, 256>>>(ew2, wh + OW2, wl + OW2);
    prep_w<DV,  HV, 1536 ><<<(HV * 1536 + 255) / 256, 256>>>(dw1, wh + OW3, wl + OW3);
    prep_w<HV,  INV, 1536><<<(INV * 1536 + 255) / 256, 256>>>(dw2, wh + OW4, wl + OW4);
    {
        size_t n = (size_t)KV * DV;
        conv_h<<<(unsigned)((n + 255) / 256), 256>>>(cb, cbh, n);
    }
    cnorm_init<<<KV / 8, 256>>>(cb, cn, cnt);

    // ---- encoder (3-pass fp16 split == fp32-accurate) ----
    mma_gemm<INV, HV, 240, 1, 3, 0, 1, HV, 256>
        <<<dim3(HV / 256, ROWS / 128), 256, SM3_256>>>(
        mh, ml, wh + OW1, wl + OW1, eb1, xh, xl, nullptr, nullptr);
    mma_gemm<HV, DV, 1536, 1, 3, 0, 0, DV, 256>
        <<<dim3(DV / 256, ROWS / 128), 256, SM3_256>>>(
        xh, xl, wh + OW2, wl + OW2, eb2, yh, yl, nullptr, nullptr);

    // ---- VQ: 1-pass partials -> exact merge -> exact re-rank of ties ----
    mma_gemm<DV, KV, 512, 0, 1, 3, 0, 0, 256>
        <<<dim3(KV / 256, ROWS / 128), 256, SM1_256>>>(
        yh, nullptr, cbh, nullptr, cn, nullptr, nullptr, nullptr, partp);
    vq_merge<<<ROWS / 8, 256>>>(partp, yh, keys, list, cnt);
    vq_exact<<<128, 256>>>(list, cnt, yh, yl, cb, cn, keys);
    gather_q<<<ROWS / 128, 256>>>(keys, cbh, xh, idx_f);

    // ---- decoder (1-pass fp16) ----
    mma_gemm<DV, HV, 1536, 1, 1, 1, 1, HV, 256>
        <<<dim3(HV / 256, ROWS / 128), 256, SM1_256>>>(
        xh, nullptr, wh + OW3, nullptr, db1, yh, nullptr, nullptr, nullptr);
    mma_gemm<HV, INV, 1536, 1, 1, 2, 0, INV, 128>
        <<<dim3(1, ROWS / 128), 256, SM1_128>>>(
        yh, nullptr, wh + OW4, nullptr, db2, nullptr, nullptr, recon, nullptr);
}

// round 16
// speedup vs baseline: 1.4316x; 1.4316x over previous
#include <cuda_runtime.h>
#include <cuda_fp16.h>
#include <cstdint>

#define BV   16
#define TV   2048
#define INV  80
#define HV   512
#define DV   512
#define KV   1024
#define ROWS (BV * TV)   // 32768

typedef unsigned long long ull;

// ---------------- scratch (device globals; no allocation allowed) ----------
__device__ __half g_mh[(size_t)ROWS * INV];
__device__ __half g_ml[(size_t)ROWS * INV];
__device__ __half g_xh[(size_t)ROWS * DV];
__device__ __half g_xl[(size_t)ROWS * DV];
__device__ __half g_yh[(size_t)ROWS * DV];
__device__ __half g_yl[(size_t)ROWS * DV];
#define OW1 0
#define OW2 131072
#define OW3 917504
#define OW4 1703936
#define WTOT (1826816 + 128 * 1536)   // pad: dec2 N-tail clamp stays in-bounds
__device__ __half g_wh[WTOT];
__device__ __half g_wl[WTOT];
__device__ __half g_cbh[(size_t)KV * DV];
__device__ float  g_cn[KV];
__device__ float4 g_part[(size_t)ROWS * 4];
__device__ ull    g_keys[ROWS];
__device__ int    g_list[ROWS];
__device__ int    g_cnt[1];
__device__ float  g_idxd[ROWS];

// ---------------- helpers --------------------------------------------------
__device__ __forceinline__ uint32_t smem_u32(const void* p) {
    uint32_t a;
    asm("{ .reg .u64 t; cvta.to.shared.u64 t, %1; cvt.u32.u64 %0, t; }"
        : "=r"(a) : "l"(p));
    return a;
}
__device__ __forceinline__ void ldsm4(uint32_t* r, uint32_t addr) {
    asm volatile("ldmatrix.sync.aligned.m8n8.x4.shared.b16 {%0,%1,%2,%3}, [%4];"
                 : "=r"(r[0]), "=r"(r[1]), "=r"(r[2]), "=r"(r[3]) : "r"(addr));
}
__device__ __forceinline__ void mma16816(float* c, const uint32_t* a, const uint32_t* b) {
    asm volatile(
        "mma.sync.aligned.m16n8k16.row.col.f32.f16.f16.f32 "
        "{%0,%1,%2,%3}, {%4,%5,%6,%7}, {%8,%9}, {%0,%1,%2,%3};"
        : "+f"(c[0]), "+f"(c[1]), "+f"(c[2]), "+f"(c[3])
        : "r"(a[0]), "r"(a[1]), "r"(a[2]), "r"(a[3]), "r"(b[0]), "r"(b[1]));
}
__device__ __forceinline__ void cp16(uint32_t dst, const void* src, uint32_t sz) {
    asm volatile("cp.async.cg.shared.global [%0], [%1], 16, %2;"
                 :: "r"(dst), "l"(src), "r"(sz));
}
#define CP_COMMIT() asm volatile("cp.async.commit_group;" ::: "memory")
#define CP_WAIT1()  asm volatile("cp.async.wait_group 1;" ::: "memory")

__device__ __forceinline__ unsigned ford(float f) {
    unsigned u = __float_as_uint(f);
    return (u & 0x80000000u) ? ~u : (u | 0x80000000u);
}
__device__ __forceinline__ float unford(unsigned u) {
    unsigned b = (u & 0x80000000u) ? (u ^ 0x80000000u) : ~u;
    return __uint_as_float(b);
}
__device__ __forceinline__ void h_split(float v, __half& h, __half& l) {
    h = __float2half_rn(v);
    l = __float2half_rn(v - __half2float(h));
}

// ---------------- prep kernels ---------------------------------------------
__global__ void split_arr(const float* __restrict__ x, __half* __restrict__ h,
                          __half* __restrict__ l, size_t n) {
    size_t i = (size_t)blockIdx.x * blockDim.x + threadIdx.x;
    if (i < n) { __half hh, ll; h_split(x[i], hh, ll); h[i] = hh; l[i] = ll; }
}
__global__ void conv_h(const float* __restrict__ x, __half* __restrict__ h, size_t n) {
    size_t i = (size_t)blockIdx.x * blockDim.x + threadIdx.x;
    if (i < n) h[i] = __float2half_rn(x[i]);
}
template<int CIN, int COUT, int KTP>
__global__ void prep_w(const float* __restrict__ w, __half* __restrict__ wh,
                       __half* __restrict__ wl) {
    int i = blockIdx.x * 256 + threadIdx.x;
    if (i >= COUT * KTP) return;
    int co = i / KTP, k = i - co * KTP;
    float v = 0.f;
    if (k < 3 * CIN) {
        int d = k / CIN, ci = k - d * CIN;
        v = w[((size_t)co * CIN + ci) * 3 + d];
    }
    __half hh, ll; h_split(v, hh, ll);
    wh[i] = hh; wl[i] = ll;
}
__global__ void cnorm_init(const float* __restrict__ cb, float* __restrict__ cn,
                           int* __restrict__ cnt) {
    int k = blockIdx.x * 8 + (threadIdx.x >> 5);
    int lane = threadIdx.x & 31;
    float s = 0.f;
    const float* row = cb + (size_t)k * DV;
    for (int c = lane; c < DV; c += 32) { float v = row[c]; s += v * v; }
    #pragma unroll
    for (int o = 16; o; o >>= 1) s += __shfl_xor_sync(0xFFFFFFFFu, s, o);
    if (lane == 0) cn[k] = s;
    if (blockIdx.x == 0 && threadIdx.x == 0) cnt[0] = 0;
}
__global__ void gather_q(const ull* __restrict__ keys, const __half* __restrict__ cbh,
                         __half* __restrict__ qh, float* __restrict__ idxf) {
    int r0 = blockIdx.x * 128;
    int tid = threadIdx.x;
    if (tid < 128)
        idxf[r0 + tid] = (float)(unsigned)(keys[r0 + tid] & 0xFFFFFFFFu);
    for (int e = tid; e < 128 * DV; e += 256) {
        int r = e >> 9, c = e & 511;
        unsigned k = (unsigned)(keys[r0 + r] & 0xFFFFFFFFu);
        qh[(size_t)(r0 + r) * DV + c] = cbh[(size_t)k * DV + c];
    }
}

// ---------------- mma.sync fp16-split GEMM, 3-stage cp.async ----------------
// CTA tile 128 x NTILE. C[m,n] = sum_k A[m,k]*B[n,k]; optional im2col.
// PASSES=3: A0B1 + A0B0 + A1B0 (fp32-accurate split).
// EPI: 0 = bias(+relu) -> split fp16 hi/lo   1 = bias(+relu) -> fp16 hi only
//      2 = bias -> fp32 out (col<NB guard)
//      3 = VQ partials (min1, k1, min2) per row over this CTA's codes ->
//          part[row*4 + blockIdx.x]; aux = ||c||^2. R7-shaped scan (no shfl).
template<int CIN, int NB, int KT, int CONV, int PASSES, int EPI, int RELU,
         int OSTR, int NTILE>
__global__ __launch_bounds__(256, 1)
void mma_gemm(const __half* __restrict__ Ah, const __half* __restrict__ Al,
              const __half* __restrict__ Bh, const __half* __restrict__ Bl,
              const float* __restrict__ aux,
              __half* __restrict__ oh, __half* __restrict__ ol,
              float* __restrict__ of, float4* __restrict__ part)
{
    constexpr int NCH    = (KT + 31) / 32;
    constexpr int KTP    = NCH * 32;
    constexpr int LDS    = 40;
    constexpr int ATILEB = 128 * LDS * 2;
    constexpr int BTILEB = NTILE * LDS * 2;
    constexpr int STB    = (PASSES == 3) ? 2 * (ATILEB + BTILEB) : (ATILEB + BTILEB);
    constexpr int S      = 3;
    constexpr int WNF    = NTILE / 64;
    constexpr int NF     = 2 * WNF;

    extern __shared__ char smem[];
    const uint32_t sb = smem_u32(smem);

    const int tid = threadIdx.x, lane = tid & 31, wid = tid >> 5;
    const int warp_m = (wid & 1) * 64;
    const int warp_n = (wid >> 1) * (16 * WNF);
    const int n0 = blockIdx.x * NTILE, m0 = blockIdx.y * 128;
    const int bb = CONV ? m0 / TV : 0;
    const int tl = CONV ? m0 % TV : 0;

    float C[4][NF][4];
    #pragma unroll
    for (int i = 0; i < 4; i++)
        #pragma unroll
        for (int j = 0; j < NF; j++)
            #pragma unroll
            for (int q = 0; q < 4; q++) C[i][j][q] = 0.f;

    uint32_t aoff[4], boff[WNF];
    #pragma unroll
    for (int mi = 0; mi < 4; mi++)
        aoff[mi] = ((warp_m + mi * 16 + (lane & 15)) * LDS + (lane >> 4) * 8) * 2;
    #pragma unroll
    for (int bj = 0; bj < WNF; bj++)
        boff[bj] = ((warp_n + bj * 16 + ((lane >> 4) << 3) + (lane & 7)) * LDS
                    + ((lane >> 3) & 1) * 8) * 2;

    auto LOADC = [&](int cc, int st) {
        const uint32_t base = sb + (uint32_t)st * STB;
        #pragma unroll
        for (int p = 0; p < 2; p++) {
            int i_ = tid + p * 256;
            int r_ = i_ >> 2, v8 = (i_ & 3) * 8;
            uint32_t doff = (uint32_t)(r_ * LDS + v8) * 2;
            int k_ = cc * 32 + v8;
            int d_  = CONV ? k_ / CIN : 0;
            int ci_ = k_ - d_ * CIN;
            bool ok = (KT == KTP) || (k_ < KT);
            size_t row_;
            if (CONV) {
                int t_ = tl + r_ + d_ - 1;
                bool tin = (t_ >= 0 && t_ < TV);
                ok = ok && tin;
                row_ = (size_t)bb * TV + (tin ? t_ : 0);
            } else {
                row_ = (size_t)(m0 + r_);
            }
            if (!ok) ci_ = 0;
            uint32_t sz = ok ? 16u : 0u;
            const size_t go = row_ * CIN + ci_;
            cp16(base + doff, Ah + go, sz);
            if (PASSES == 3) cp16(base + ATILEB + doff, Al + go, sz);
        }
        const uint32_t bbase = base + (PASSES == 3 ? 2 : 1) * ATILEB;
        #pragma unroll
        for (int p = 0; p < NTILE / 64; p++) {
            int i_ = tid + p * 256;
            int r_ = i_ >> 2, v8 = (i_ & 3) * 8;
            uint32_t doff = (uint32_t)(r_ * LDS + v8) * 2;
            int k_ = cc * 32 + v8;
            bool ok = ((NB % NTILE) == 0) || ((n0 + r_) < NB);
            int rb = ok ? (n0 + r_) : 0;
            uint32_t sz = ok ? 16u : 0u;
            const size_t go = (size_t)rb * KTP + k_;
            cp16(bbase + doff, Bh + go, sz);
            if (PASSES == 3) cp16(bbase + BTILEB + doff, Bl + go, sz);
        }
    };

#define MMASET() do {                                                          \
    _Pragma("unroll")                                                          \
    for (int mi = 0; mi < 4; mi++)                                             \
        _Pragma("unroll")                                                      \
        for (int bj = 0; bj < WNF; bj++) {                                     \
            mma16816(C[mi][bj * 2],     Af[mi], &Bf[bj][0]);                   \
            mma16816(C[mi][bj * 2 + 1], Af[mi], &Bf[bj][2]);                   \
        } } while (0)

    LOADC(0, 0); CP_COMMIT();
    LOADC(1, 1); CP_COMMIT();

    for (int c = 0; c < NCH; c++) {
        CP_WAIT1();
        __syncthreads();
        const int st = c % S;
        const uint32_t a0b = sb + (uint32_t)st * STB;
        const uint32_t a1b = a0b + ATILEB;
        const uint32_t b0b = a0b + (PASSES == 3 ? 2 : 1) * ATILEB;
        const uint32_t b1b = b0b + BTILEB;

        #pragma unroll
        for (int ks = 0; ks < 2; ks++) {
            uint32_t Af[4][4], Bf[WNF][4];
            const uint32_t ko = ks * 32;
            if (PASSES == 3) {
                #pragma unroll
                for (int mi = 0; mi < 4; mi++) ldsm4(Af[mi], a0b + aoff[mi] + ko);
                #pragma unroll
                for (int bj = 0; bj < WNF; bj++) ldsm4(Bf[bj], b1b + boff[bj] + ko);
                MMASET();
                #pragma unroll
                for (int bj = 0; bj < WNF; bj++) ldsm4(Bf[bj], b0b + boff[bj] + ko);
                MMASET();
                #pragma unroll
                for (int mi = 0; mi < 4; mi++) ldsm4(Af[mi], a1b + aoff[mi] + ko);
                MMASET();
            } else {
                #pragma unroll
                for (int mi = 0; mi < 4; mi++) ldsm4(Af[mi], a0b + aoff[mi] + ko);
                #pragma unroll
                for (int bj = 0; bj < WNF; bj++) ldsm4(Bf[bj], b0b + boff[bj] + ko);
                MMASET();
            }
        }
        const int nc = c + S - 1;
        if (nc < NCH) LOADC(nc, nc % S);
        CP_COMMIT();
    }

    const int gid = lane >> 2, tig = lane & 3;

    if (EPI <= 2) {
        #pragma unroll
        for (int fi = 0; fi < NF; fi++) {
            int cg = n0 + warp_n + fi * 8 + 2 * tig;
            bool c0ok = (EPI != 2) || (cg < NB);
            bool c1ok = (EPI != 2) || (cg + 1 < NB);
            float bv0 = c0ok ? aux[cg] : 0.f;
            float bv1 = c1ok ? aux[cg + 1] : 0.f;
            #pragma unroll
            for (int mi = 0; mi < 4; mi++) {
                int r0 = m0 + warp_m + mi * 16 + gid;
                float v00 = C[mi][fi][0] + bv0, v01 = C[mi][fi][1] + bv1;
                float v10 = C[mi][fi][2] + bv0, v11 = C[mi][fi][3] + bv1;
                if (RELU) {
                    v00 = fmaxf(v00, 0.f); v01 = fmaxf(v01, 0.f);
                    v10 = fmaxf(v10, 0.f); v11 = fmaxf(v11, 0.f);
                }
                if (EPI == 2) {
                    if (c0ok) { of[(size_t)r0 * OSTR + cg] = v00;
                                of[(size_t)(r0 + 8) * OSTR + cg] = v10; }
                    if (c1ok) { of[(size_t)r0 * OSTR + cg + 1] = v01;
                                of[(size_t)(r0 + 8) * OSTR + cg + 1] = v11; }
                } else {
                    __half h00, h01, h10, h11, l00, l01, l10, l11;
                    h_split(v00, h00, l00); h_split(v01, h01, l01);
                    h_split(v10, h10, l10); h_split(v11, h11, l11);
                    *(__half2*)(oh + (size_t)r0 * OSTR + cg)       = __halves2half2(h00, h01);
                    *(__half2*)(oh + (size_t)(r0 + 8) * OSTR + cg) = __halves2half2(h10, h11);
                    if (EPI == 0) {
                        *(__half2*)(ol + (size_t)r0 * OSTR + cg)       = __halves2half2(l00, l01);
                        *(__half2*)(ol + (size_t)(r0 + 8) * OSTR + cg) = __halves2half2(l10, l11);
                    }
                }
            }
        }
    } else {
        // EPI == 3: R7-shaped per-thread scan (fi outer, mi inner) + best2.
        float best[8], best2[8]; unsigned bk[8];
        #pragma unroll
        for (int i = 0; i < 8; i++) { best[i] = 3.4e38f; best2[i] = 3.4e38f; bk[i] = 0; }
        #pragma unroll
        for (int fi = 0; fi < NF; fi++) {
            int cg = n0 + warp_n + fi * 8 + 2 * tig;
            float cn0 = aux[cg], cn1 = aux[cg + 1];
            #pragma unroll
            for (int mi = 0; mi < 4; mi++) {
                float d;
                d = cn0 - 2.f * C[mi][fi][0];
                if (d < best[2 * mi]) { best2[2 * mi] = best[2 * mi]; best[2 * mi] = d; bk[2 * mi] = (unsigned)cg; }
                else if (d < best2[2 * mi]) best2[2 * mi] = d;
                d = cn1 - 2.f * C[mi][fi][1];
                if (d < best[2 * mi]) { best2[2 * mi] = best[2 * mi]; best[2 * mi] = d; bk[2 * mi] = (unsigned)(cg + 1); }
                else if (d < best2[2 * mi]) best2[2 * mi] = d;
                d = cn0 - 2.f * C[mi][fi][2];
                if (d < best[2 * mi + 1]) { best2[2 * mi + 1] = best[2 * mi + 1]; best[2 * mi + 1] = d; bk[2 * mi + 1] = (unsigned)cg; }
                else if (d < best2[2 * mi + 1]) best2[2 * mi + 1] = d;
                d = cn1 - 2.f * C[mi][fi][3];
                if (d < best[2 * mi + 1]) { best2[2 * mi + 1] = best[2 * mi + 1]; best[2 * mi + 1] = d; bk[2 * mi + 1] = (unsigned)(cg + 1); }
                else if (d < best2[2 * mi + 1]) best2[2 * mi + 1] = d;
            }
        }
        __syncthreads();
        ull* red = (ull*)smem;                       // [128] packed min1|k
        unsigned* red2 = (unsigned*)(red + 128);     // [128] ford(min2)
        if (tid < 128) { red[tid] = ~0ULL; red2[tid] = 0xFFFFFFFFu; }
        __syncthreads();
        #pragma unroll
        for (int mi = 0; mi < 4; mi++)
            #pragma unroll
            for (int h = 0; h < 2; h++) {
                int rl = warp_m + mi * 16 + gid + 8 * h;
                ull key = ((ull)ford(best[2 * mi + h]) << 32) | (ull)bk[2 * mi + h];
                atomicMin(&red[rl], key);
            }
        __syncthreads();
        #pragma unroll
        for (int mi = 0; mi < 4; mi++)
            #pragma unroll
            for (int h = 0; h < 2; h++) {
                int rl = warp_m + mi * 16 + gid + 8 * h;
                int s = 2 * mi + h;
                ull mykey = ((ull)ford(best[s]) << 32) | (ull)bk[s];
                float cand = (mykey == red[rl]) ? best2[s] : best[s];
                atomicMin(&red2[rl], ford(cand));
            }
        __syncthreads();
        if (tid < 128) {
            ull w = red[tid];
            float m1 = unford((unsigned)(w >> 32));
            float m2 = unford(red2[tid]);
            part[(size_t)(m0 + tid) * 4 + blockIdx.x] =
                make_float4(m1, __uint_as_float((unsigned)(w & 0xFFFFFFFFu)), m2, 0.f);
        }
    }
#undef MMASET
}

// ---------------- VQ merge: exact min1/min2 across the 4 N-block partials ---
__global__ __launch_bounds__(256)
void vq_merge(const float4* __restrict__ part, const __half* __restrict__ yh,
              ull* __restrict__ keys, int* __restrict__ list,
              int* __restrict__ cnt)
{
    const int w = threadIdx.x >> 5, lane = threadIdx.x & 31;
    const int row = blockIdx.x * 8 + w;
    const uint4* zp = (const uint4*)(yh + (size_t)row * DV);
    float zsq = 0.f;
    #pragma unroll
    for (int it = 0; it < 2; it++) {
        uint4 v = zp[lane + it * 32];
        const __half2* hp = (const __half2*)&v;
        #pragma unroll
        for (int j = 0; j < 4; j++) {
            float2 f = __half22float2(hp[j]);
            zsq += f.x * f.x + f.y * f.y;
        }
    }
    #pragma unroll
    for (int o = 16; o; o >>= 1) zsq += __shfl_xor_sync(0xFFFFFFFFu, zsq, o);
    if (lane == 0) {
        float m1 = 3.4e38f, m2 = 3.4e38f; unsigned k1 = 0;
        #pragma unroll
        for (int b = 0; b < 4; b++) {
            float4 e = part[(size_t)row * 4 + b];
            unsigned ek = __float_as_uint(e.y);
            if (e.x < m1 || (e.x == m1 && ek < k1)) {
                m2 = fminf(m1, e.z); m1 = e.x; k1 = ek;
            } else {
                m2 = fminf(m2, e.x);
            }
        }
        keys[row] = (((ull)ford(m1)) << 32) | (ull)k1;
        float eps = 0.02f * sqrtf(zsq) + 0.05f;
        if (m2 - m1 < eps) {
            int p = atomicAdd(cnt, 1);
            list[p] = row;
        }
    }
}

// ---------------- VQ stage 2: exact fp32 re-rank for flagged rows -----------
__global__ __launch_bounds__(256)
void vq_exact(const int* __restrict__ list, const int* __restrict__ cnt,
              const __half* __restrict__ yh, const __half* __restrict__ yl,
              const float* __restrict__ cb, const float* __restrict__ cn,
              ull* __restrict__ keys)
{
    __shared__ __align__(16) float zs[16][516];
    __shared__ ull skeys[16];
    const int count = cnt[0];
    const int tid = threadIdx.x;

    for (int b0 = blockIdx.x * 16; b0 < count; b0 += gridDim.x * 16) {
        int nb = min(16, count - b0);
        __syncthreads();
        if (tid < 16) skeys[tid] = ~0ULL;
        for (int e = tid; e < nb * 512; e += 256) {
            int r = e >> 9, i = e & 511;
            size_t ro = (size_t)list[b0 + r] * DV + i;
            zs[r][i] = __half2float(yh[ro]) + __half2float(yl[ro]);
        }
        __syncthreads();
        for (int cc = 0; cc < 4; cc++) {
            int code = tid + cc * 256;
            const float4* cr = (const float4*)(cb + (size_t)code * DV);
            float acc[16];
            #pragma unroll
            for (int r = 0; r < 16; r++) acc[r] = 0.f;
            for (int i4 = 0; i4 < 128; i4++) {
                float4 wv = cr[i4];
                #pragma unroll
                for (int r = 0; r < 16; r++) {
                    float4 zv = *(const float4*)&zs[r][i4 * 4];
                    acc[r] += zv.x * wv.x + zv.y * wv.y + zv.z * wv.z + zv.w * wv.w;
                }
            }
            float c2v = cn[code];
            for (int r = 0; r < nb; r++) {
                float d = c2v - 2.f * acc[r];
                atomicMin(&skeys[r], (((ull)ford(d)) << 32) | (ull)(unsigned)code);
            }
        }
        __syncthreads();
        if (tid < nb) keys[list[b0 + tid]] = skeys[tid];
    }
}

// ---------------- launch ----------------------------------------------------
extern "C" void kernel_launch(void* const* d_in, const int* in_sizes, int n_in,
                              void* d_out, int out_size)
{
    const float* mels = (const float*)d_in[0];
    const float* ew1  = (const float*)d_in[1];
    const float* eb1  = (const float*)d_in[2];
    const float* ew2  = (const float*)d_in[3];
    const float* eb2  = (const float*)d_in[4];
    const float* cb   = (const float*)d_in[5];
    const float* dw1  = (const float*)d_in[6];
    const float* db1  = (const float*)d_in[7];
    const float* dw2  = (const float*)d_in[8];
    const float* db2  = (const float*)d_in[9];

    float* out = (float*)d_out;

    __half *mh, *ml, *xh, *xl, *yh, *yl, *wh, *wl, *cbh;
    float *cn, *idxd;
    float4 *partp;
    ull *keys;
    int *list, *cnt;
    cudaGetSymbolAddress((void**)&mh, g_mh);   cudaGetSymbolAddress((void**)&ml, g_ml);
    cudaGetSymbolAddress((void**)&xh, g_xh);   cudaGetSymbolAddress((void**)&xl, g_xl);
    cudaGetSymbolAddress((void**)&yh, g_yh);   cudaGetSymbolAddress((void**)&yl, g_yl);
    cudaGetSymbolAddress((void**)&wh, g_wh);   cudaGetSymbolAddress((void**)&wl, g_wl);
    cudaGetSymbolAddress((void**)&cbh, g_cbh);
    cudaGetSymbolAddress((void**)&cn, g_cn);
    cudaGetSymbolAddress((void**)&partp, g_part);
    cudaGetSymbolAddress((void**)&keys, g_keys);
    cudaGetSymbolAddress((void**)&list, g_list);
    cudaGetSymbolAddress((void**)&cnt, g_cnt);
    cudaGetSymbolAddress((void**)&idxd, g_idxd);

    float* recon = out;
    float* idx_f = (out_size >= (int)((size_t)ROWS * INV + ROWS))
                     ? out + (size_t)ROWS * INV
                     : idxd;

    constexpr int SM3_256 = 3 * 61440;   // 184320
    constexpr int SM1_256 = 3 * 30720;   //  92160
    constexpr int SM1_128 = 3 * 20480;   //  61440
    static bool attr_done = false;
    if (!attr_done) {
        cudaFuncSetAttribute(mma_gemm<INV, HV, 240, 1, 3, 0, 1, HV, 256>,
                             cudaFuncAttributeMaxDynamicSharedMemorySize, SM3_256);
        cudaFuncSetAttribute(mma_gemm<HV, DV, 1536, 1, 3, 0, 0, DV, 256>,
                             cudaFuncAttributeMaxDynamicSharedMemorySize, SM3_256);
        cudaFuncSetAttribute(mma_gemm<DV, KV, 512, 0, 1, 3, 0, 0, 256>,
                             cudaFuncAttributeMaxDynamicSharedMemorySize, SM1_256);
        cudaFuncSetAttribute(mma_gemm<DV, HV, 1536, 1, 1, 1, 1, HV, 256>,
                             cudaFuncAttributeMaxDynamicSharedMemorySize, SM1_256);
        cudaFuncSetAttribute(mma_gemm<HV, INV, 1536, 1, 1, 2, 0, INV, 128>,
                             cudaFuncAttributeMaxDynamicSharedMemorySize, SM1_128);
        attr_done = true;
    }

    // ---- prep ----
    {
        size_t n = (size_t)ROWS * INV;
        split_arr<<<(unsigned)((n + 255) / 256), 256>>>(mels, mh, ml, n);
    }
    prep_w<INV, HV, 256  ><<<(HV * 256  + 255) / 256, 256>>>(ew1, wh + OW1, wl + OW1);
    prep_w<HV,  DV, 1536 ><<<(DV * 1536 + 255) / 256, 256>>>(ew2, wh + OW2, wl + OW2);
    prep_w<DV,  HV, 1536 ><<<(HV * 1536 + 255) / 256, 256>>>(dw1, wh + OW3, wl + OW3);
    prep_w<HV,  INV, 1536><<<(INV * 1536 + 255) / 256, 256>>>(dw2, wh + OW4, wl + OW4);
    {
        size_t n = (size_t)KV * DV;
        conv_h<<<(unsigned)((n + 255) / 256), 256>>>(cb, cbh, n);
    }
    cnorm_init<<<KV / 8, 256>>>(cb, cn, cnt);

    // ---- encoder (3-pass fp16 split == fp32-accurate) ----
    mma_gemm<INV, HV, 240, 1, 3, 0, 1, HV, 256>
        <<<dim3(HV / 256, ROWS / 128), 256, SM3_256>>>(
        mh, ml, wh + OW1, wl + OW1, eb1, xh, xl, nullptr, nullptr);
    mma_gemm<HV, DV, 1536, 1, 3, 0, 0, DV, 256>
        <<<dim3(DV / 256, ROWS / 128), 256, SM3_256>>>(
        xh, xl, wh + OW2, wl + OW2, eb2, yh, yl, nullptr, nullptr);

    // ---- VQ: 1-pass partials -> exact merge -> exact re-rank of ties ----
    mma_gemm<DV, KV, 512, 0, 1, 3, 0, 0, 256>
        <<<dim3(KV / 256, ROWS / 128), 256, SM1_256>>>(
        yh, nullptr, cbh, nullptr, cn, nullptr, nullptr, nullptr, partp);
    vq_merge<<<ROWS / 8, 256>>>(partp, yh, keys, list, cnt);
    vq_exact<<<128, 256>>>(list, cnt, yh, yl, cb, cn, keys);
    gather_q<<<ROWS / 128, 256>>>(keys, cbh, xh, idx_f);

    // ---- decoder (1-pass fp16) ----
    mma_gemm<DV, HV, 1536, 1, 1, 1, 1, HV, 256>
        <<<dim3(HV / 256, ROWS / 128), 256, SM1_256>>>(
        xh, nullptr, wh + OW3, nullptr, db1, yh, nullptr, nullptr, nullptr);
    mma_gemm<HV, INV, 1536, 1, 1, 2, 0, INV, 128>
        <<<dim3(1, ROWS / 128), 256, SM1_128>>>(
        yh, nullptr, wh + OW4, nullptr, db2, nullptr, nullptr, recon, nullptr);
}

// round 17
// speedup vs baseline: 1.5594x; 1.0892x over previous
#include <cuda_runtime.h>
#include <cuda_fp16.h>
#include <cstdint>

#define BV   16
#define TV   2048
#define INV  80
#define HV   512
#define DV   512
#define KV   1024
#define ROWS (BV * TV)   // 32768

typedef unsigned long long ull;

// ---------------- scratch (device globals; no allocation allowed) ----------
__device__ __half g_mh[(size_t)ROWS * INV];
__device__ __half g_ml[(size_t)ROWS * INV];
__device__ __half g_xh[(size_t)ROWS * DV];
__device__ __half g_xl[(size_t)ROWS * DV];
__device__ __half g_yh[(size_t)ROWS * DV];
__device__ __half g_yl[(size_t)ROWS * DV];
#define OW1 0
#define OW2 131072
#define OW3 917504
#define OW4 1703936
#define WTOT (1826816 + 128 * 1536)   // pad: dec2 N-tail clamp stays in-bounds
__device__ __half g_wh[WTOT];
__device__ __half g_wl[WTOT];
__device__ __half g_cbh[(size_t)KV * DV];
__device__ __half g_cbl[(size_t)KV * DV];
__device__ float  g_cn[KV];
__device__ ull    g_keys[ROWS];
__device__ float  g_idxd[ROWS];

// ---------------- helpers --------------------------------------------------
__device__ __forceinline__ uint32_t smem_u32(const void* p) {
    uint32_t a;
    asm("{ .reg .u64 t; cvta.to.shared.u64 t, %1; cvt.u32.u64 %0, t; }"
        : "=r"(a) : "l"(p));
    return a;
}
__device__ __forceinline__ void ldsm4(uint32_t* r, uint32_t addr) {
    asm volatile("ldmatrix.sync.aligned.m8n8.x4.shared.b16 {%0,%1,%2,%3}, [%4];"
                 : "=r"(r[0]), "=r"(r[1]), "=r"(r[2]), "=r"(r[3]) : "r"(addr));
}
__device__ __forceinline__ void mma16816(float* c, const uint32_t* a, const uint32_t* b) {
    asm volatile(
        "mma.sync.aligned.m16n8k16.row.col.f32.f16.f16.f32 "
        "{%0,%1,%2,%3}, {%4,%5,%6,%7}, {%8,%9}, {%0,%1,%2,%3};"
        : "+f"(c[0]), "+f"(c[1]), "+f"(c[2]), "+f"(c[3])
        : "r"(a[0]), "r"(a[1]), "r"(a[2]), "r"(a[3]), "r"(b[0]), "r"(b[1]));
}
__device__ __forceinline__ void cp16(uint32_t dst, const void* src, uint32_t sz) {
    asm volatile("cp.async.cg.shared.global [%0], [%1], 16, %2;"
                 :: "r"(dst), "l"(src), "r"(sz));
}
#define CP_COMMIT() asm volatile("cp.async.commit_group;" ::: "memory")
#define CP_WAIT1()  asm volatile("cp.async.wait_group 1;" ::: "memory")

__device__ __forceinline__ unsigned ford(float f) {
    unsigned u = __float_as_uint(f);
    return (u & 0x80000000u) ? ~u : (u | 0x80000000u);
}
__device__ __forceinline__ void h_split(float v, __half& h, __half& l) {
    h = __float2half_rn(v);
    l = __float2half_rn(v - __half2float(h));
}

// ---------------- prep kernels ---------------------------------------------
__global__ void split_arr(const float* __restrict__ x, __half* __restrict__ h,
                          __half* __restrict__ l, size_t n) {
    size_t i = (size_t)blockIdx.x * blockDim.x + threadIdx.x;
    if (i < n) { __half hh, ll; h_split(x[i], hh, ll); h[i] = hh; l[i] = ll; }
}
template<int CIN, int COUT, int KTP>
__global__ void prep_w(const float* __restrict__ w, __half* __restrict__ wh,
                       __half* __restrict__ wl) {
    int i = blockIdx.x * 256 + threadIdx.x;
    if (i >= COUT * KTP) return;
    int co = i / KTP, k = i - co * KTP;
    float v = 0.f;
    if (k < 3 * CIN) {
        int d = k / CIN, ci = k - d * CIN;
        v = w[((size_t)co * CIN + ci) * 3 + d];
    }
    __half hh, ll; h_split(v, hh, ll);
    wh[i] = hh; wl[i] = ll;
}
__global__ void cnorm_init(const float* __restrict__ cb, float* __restrict__ cn,
                           ull* __restrict__ keys) {
    int k = blockIdx.x * 8 + (threadIdx.x >> 5);
    int lane = threadIdx.x & 31;
    float s = 0.f;
    const float* row = cb + (size_t)k * DV;
    for (int c = lane; c < DV; c += 32) { float v = row[c]; s += v * v; }
    #pragma unroll
    for (int o = 16; o; o >>= 1) s += __shfl_xor_sync(0xFFFFFFFFu, s, o);
    if (lane == 0) cn[k] = s;
    int i = blockIdx.x * 256 + threadIdx.x;   // 128 blocks * 256 = 32768
    if (i < ROWS) keys[i] = ~0ULL;
}
__global__ void idx_out(const ull* __restrict__ keys, float* __restrict__ idxf) {
    int i = blockIdx.x * 256 + threadIdx.x;
    if (i < ROWS)
        idxf[i] = (float)(unsigned)(keys[i] & 0xFFFFFFFFu);
}

// ---------------- mma.sync fp16-split GEMM, 3-stage cp.async ----------------
// CTA tile 128 x NTILE (NTILE 256: warp 64x64, NTILE 128: warp 64x32).
// C[m, n] = sum_k A[m,k] * B[n,k];  A via optional conv im2col (k = d*CIN+ci,
// row shift d-1).  GATHER: A row r is cbh[keys[r] & 0xffffffff] (fused VQ
// gather for the decoder).  PASSES=3: A0B1 + A0B0 + A1B0 (fp32-accurate).
// EPI: 0 = bias(+relu) -> split fp16 hi/lo   1 = bias(+relu) -> fp16 hi only
//      2 = bias -> fp32 out (col<NB guard)   3 = VQ argmin (aux = ||c||^2)
template<int CIN, int NB, int KT, int CONV, int PASSES, int EPI, int RELU,
         int OSTR, int NTILE, int GATHER>
__global__ __launch_bounds__(256, 1)
void mma_gemm(const __half* __restrict__ Ah, const __half* __restrict__ Al,
              const __half* __restrict__ Bh, const __half* __restrict__ Bl,
              const float* __restrict__ aux,
              __half* __restrict__ oh, __half* __restrict__ ol,
              float* __restrict__ of, ull* __restrict__ keys,
              const ull* __restrict__ gkeys)
{
    constexpr int NCH    = (KT + 31) / 32;
    constexpr int KTP    = NCH * 32;
    constexpr int LDS    = 40;
    constexpr int ATILEB = 128 * LDS * 2;
    constexpr int BTILEB = NTILE * LDS * 2;
    constexpr int STB    = (PASSES == 3) ? 2 * (ATILEB + BTILEB) : (ATILEB + BTILEB);
    constexpr int S      = 3;
    constexpr int WNF    = NTILE / 64;
    constexpr int NF     = 2 * WNF;

    extern __shared__ char smem[];
    const uint32_t sb = smem_u32(smem);

    const int tid = threadIdx.x, lane = tid & 31, wid = tid >> 5;
    const int warp_m = (wid & 1) * 64;
    const int warp_n = (wid >> 1) * (16 * WNF);
    const int n0 = blockIdx.x * NTILE, m0 = blockIdx.y * 128;
    const int bb = CONV ? m0 / TV : 0;
    const int tl = CONV ? m0 % TV : 0;

    float C[4][NF][4];
    #pragma unroll
    for (int i = 0; i < 4; i++)
        #pragma unroll
        for (int j = 0; j < NF; j++)
            #pragma unroll
            for (int q = 0; q < 4; q++) C[i][j][q] = 0.f;

    uint32_t aoff[4], boff[WNF];
    #pragma unroll
    for (int mi = 0; mi < 4; mi++)
        aoff[mi] = ((warp_m + mi * 16 + (lane & 15)) * LDS + (lane >> 4) * 8) * 2;
    #pragma unroll
    for (int bj = 0; bj < WNF; bj++)
        boff[bj] = ((warp_n + bj * 16 + ((lane >> 4) << 3) + (lane & 7)) * LDS
                    + ((lane >> 3) & 1) * 8) * 2;

    auto LOADC = [&](int cc, int st) {
        const uint32_t base = sb + (uint32_t)st * STB;
        #pragma unroll
        for (int p = 0; p < 2; p++) {
            int i_ = tid + p * 256;
            int r_ = i_ >> 2, v8 = (i_ & 3) * 8;
            uint32_t doff = (uint32_t)(r_ * LDS + v8) * 2;
            int k_ = cc * 32 + v8;
            int d_  = CONV ? k_ / CIN : 0;
            int ci_ = k_ - d_ * CIN;
            bool ok = (KT == KTP) || (k_ < KT);
            size_t row_;
            if (CONV) {
                int t_ = tl + r_ + d_ - 1;
                bool tin = (t_ >= 0 && t_ < TV);
                ok = ok && tin;
                row_ = (size_t)bb * TV + (tin ? t_ : 0);
            } else {
                row_ = (size_t)(m0 + r_);
            }
            if (!ok) ci_ = 0;
            uint32_t sz = ok ? 16u : 0u;
            size_t go;
            if (GATHER) {
                unsigned kk = (unsigned)(gkeys[row_] & 0xFFFFFFFFu);
                go = (size_t)kk * CIN + ci_;
            } else {
                go = row_ * CIN + ci_;
            }
            cp16(base + doff, Ah + go, sz);
            if (PASSES == 3) cp16(base + ATILEB + doff, Al + go, sz);
        }
        const uint32_t bbase = base + (PASSES == 3 ? 2 : 1) * ATILEB;
        #pragma unroll
        for (int p = 0; p < NTILE / 64; p++) {
            int i_ = tid + p * 256;
            int r_ = i_ >> 2, v8 = (i_ & 3) * 8;
            uint32_t doff = (uint32_t)(r_ * LDS + v8) * 2;
            int k_ = cc * 32 + v8;
            bool ok = ((NB % NTILE) == 0) || ((n0 + r_) < NB);
            int rb = ok ? (n0 + r_) : 0;
            uint32_t sz = ok ? 16u : 0u;
            const size_t go = (size_t)rb * KTP + k_;
            cp16(bbase + doff, Bh + go, sz);
            if (PASSES == 3) cp16(bbase + BTILEB + doff, Bl + go, sz);
        }
    };

#define MMASET() do {                                                          \
    _Pragma("unroll")                                                          \
    for (int mi = 0; mi < 4; mi++)                                             \
        _Pragma("unroll")                                                      \
        for (int bj = 0; bj < WNF; bj++) {                                     \
            mma16816(C[mi][bj * 2],     Af[mi], &Bf[bj][0]);                   \
            mma16816(C[mi][bj * 2 + 1], Af[mi], &Bf[bj][2]);                   \
        } } while (0)

    LOADC(0, 0); CP_COMMIT();
    LOADC(1, 1); CP_COMMIT();

    for (int c = 0; c < NCH; c++) {
        CP_WAIT1();
        __syncthreads();
        const int st = c % S;
        const uint32_t a0b = sb + (uint32_t)st * STB;
        const uint32_t a1b = a0b + ATILEB;
        const uint32_t b0b = a0b + (PASSES == 3 ? 2 : 1) * ATILEB;
        const uint32_t b1b = b0b + BTILEB;

        #pragma unroll
        for (int ks = 0; ks < 2; ks++) {
            uint32_t Af[4][4], Bf[WNF][4];
            const uint32_t ko = ks * 32;
            if (PASSES == 3) {
                #pragma unroll
                for (int mi = 0; mi < 4; mi++) ldsm4(Af[mi], a0b + aoff[mi] + ko);
                #pragma unroll
                for (int bj = 0; bj < WNF; bj++) ldsm4(Bf[bj], b1b + boff[bj] + ko);
                MMASET();
                #pragma unroll
                for (int bj = 0; bj < WNF; bj++) ldsm4(Bf[bj], b0b + boff[bj] + ko);
                MMASET();
                #pragma unroll
                for (int mi = 0; mi < 4; mi++) ldsm4(Af[mi], a1b + aoff[mi] + ko);
                MMASET();
            } else {
                #pragma unroll
                for (int mi = 0; mi < 4; mi++) ldsm4(Af[mi], a0b + aoff[mi] + ko);
                #pragma unroll
                for (int bj = 0; bj < WNF; bj++) ldsm4(Bf[bj], b0b + boff[bj] + ko);
                MMASET();
            }
        }
        const int nc = c + S - 1;
        if (nc < NCH) LOADC(nc, nc % S);
        CP_COMMIT();
    }

    const int gid = lane >> 2, tig = lane & 3;

    if (EPI <= 2) {
        #pragma unroll
        for (int fi = 0; fi < NF; fi++) {
            int cg = n0 + warp_n + fi * 8 + 2 * tig;
            bool c0ok = (EPI != 2) || (cg < NB);
            bool c1ok = (EPI != 2) || (cg + 1 < NB);
            float bv0 = c0ok ? aux[cg] : 0.f;
            float bv1 = c1ok ? aux[cg + 1] : 0.f;
            #pragma unroll
            for (int mi = 0; mi < 4; mi++) {
                int r0 = m0 + warp_m + mi * 16 + gid;
                float v00 = C[mi][fi][0] + bv0, v01 = C[mi][fi][1] + bv1;
                float v10 = C[mi][fi][2] + bv0, v11 = C[mi][fi][3] + bv1;
                if (RELU) {
                    v00 = fmaxf(v00, 0.f); v01 = fmaxf(v01, 0.f);
                    v10 = fmaxf(v10, 0.f); v11 = fmaxf(v11, 0.f);
                }
                if (EPI == 2) {
                    if (c0ok) { of[(size_t)r0 * OSTR + cg] = v00;
                                of[(size_t)(r0 + 8) * OSTR + cg] = v10; }
                    if (c1ok) { of[(size_t)r0 * OSTR + cg + 1] = v01;
                                of[(size_t)(r0 + 8) * OSTR + cg + 1] = v11; }
                } else {
                    __half h00, h01, h10, h11, l00, l01, l10, l11;
                    h_split(v00, h00, l00); h_split(v01, h01, l01);
                    h_split(v10, h10, l10); h_split(v11, h11, l11);
                    *(__half2*)(oh + (size_t)r0 * OSTR + cg)       = __halves2half2(h00, h01);
                    *(__half2*)(oh + (size_t)(r0 + 8) * OSTR + cg) = __halves2half2(h10, h11);
                    if (EPI == 0) {
                        *(__half2*)(ol + (size_t)r0 * OSTR + cg)       = __halves2half2(l00, l01);
                        *(__half2*)(ol + (size_t)(r0 + 8) * OSTR + cg) = __halves2half2(l10, l11);
                    }
                }
            }
        }
    } else {
        float best[8]; unsigned bk[8];
        #pragma unroll
        for (int i = 0; i < 8; i++) { best[i] = 3.4e38f; bk[i] = 0; }
        #pragma unroll
        for (int fi = 0; fi < NF; fi++) {
            int cg = n0 + warp_n + fi * 8 + 2 * tig;
            float cn0 = aux[cg], cn1 = aux[cg + 1];
            #pragma unroll
            for (int mi = 0; mi < 4; mi++) {
                float d;
                d = cn0 - 2.f * C[mi][fi][0];
                if (d < best[2 * mi]) { best[2 * mi] = d; bk[2 * mi] = (unsigned)cg; }
                d = cn1 - 2.f * C[mi][fi][1];
                if (d < best[2 * mi]) { best[2 * mi] = d; bk[2 * mi] = (unsigned)(cg + 1); }
                d = cn0 - 2.f * C[mi][fi][2];
                if (d < best[2 * mi + 1]) { best[2 * mi + 1] = d; bk[2 * mi + 1] = (unsigned)cg; }
                d = cn1 - 2.f * C[mi][fi][3];
                if (d < best[2 * mi + 1]) { best[2 * mi + 1] = d; bk[2 * mi + 1] = (unsigned)(cg + 1); }
            }
        }
        __syncthreads();
        ull* red = (ull*)smem;
        if (tid < 128) red[tid] = ~0ULL;
        __syncthreads();
        #pragma unroll
        for (int mi = 0; mi < 4; mi++)
            #pragma unroll
            for (int h = 0; h < 2; h++) {
                int rl = warp_m + mi * 16 + gid + 8 * h;
                ull key = ((ull)ford(best[2 * mi + h]) << 32) | (ull)bk[2 * mi + h];
                atomicMin(&red[rl], key);
            }
        __syncthreads();
        if (tid < 128) atomicMin(&keys[m0 + tid], red[tid]);
    }
#undef MMASET
}

// ---------------- launch ----------------------------------------------------
extern "C" void kernel_launch(void* const* d_in, const int* in_sizes, int n_in,
                              void* d_out, int out_size)
{
    const float* mels = (const float*)d_in[0];
    const float* ew1  = (const float*)d_in[1];
    const float* eb1  = (const float*)d_in[2];
    const float* ew2  = (const float*)d_in[3];
    const float* eb2  = (const float*)d_in[4];
    const float* cb   = (const float*)d_in[5];
    const float* dw1  = (const float*)d_in[6];
    const float* db1  = (const float*)d_in[7];
    const float* dw2  = (const float*)d_in[8];
    const float* db2  = (const float*)d_in[9];

    float* out = (float*)d_out;

    __half *mh, *ml, *xh, *xl, *yh, *yl, *wh, *wl, *cbh, *cbl;
    float *cn, *idxd;
    ull *keys;
    cudaGetSymbolAddress((void**)&mh, g_mh);   cudaGetSymbolAddress((void**)&ml, g_ml);
    cudaGetSymbolAddress((void**)&xh, g_xh);   cudaGetSymbolAddress((void**)&xl, g_xl);
    cudaGetSymbolAddress((void**)&yh, g_yh);   cudaGetSymbolAddress((void**)&yl, g_yl);
    cudaGetSymbolAddress((void**)&wh, g_wh);   cudaGetSymbolAddress((void**)&wl, g_wl);
    cudaGetSymbolAddress((void**)&cbh, g_cbh); cudaGetSymbolAddress((void**)&cbl, g_cbl);
    cudaGetSymbolAddress((void**)&cn, g_cn);
    cudaGetSymbolAddress((void**)&keys, g_keys);
    cudaGetSymbolAddress((void**)&idxd, g_idxd);

    float* recon = out;
    float* idx_f = (out_size >= (int)((size_t)ROWS * INV + ROWS))
                     ? out + (size_t)ROWS * INV
                     : idxd;

    constexpr int SM3_256 = 3 * 61440;   // 184320
    constexpr int SM1_256 = 3 * 30720;   //  92160
    constexpr int SM1_128 = 3 * 20480;   //  61440
    static bool attr_done = false;
    if (!attr_done) {
        cudaFuncSetAttribute(mma_gemm<INV, HV, 240, 1, 3, 0, 1, HV, 256, 0>,
                             cudaFuncAttributeMaxDynamicSharedMemorySize, SM3_256);
        cudaFuncSetAttribute(mma_gemm<HV, DV, 1536, 1, 3, 0, 0, DV, 256, 0>,
                             cudaFuncAttributeMaxDynamicSharedMemorySize, SM3_256);
        cudaFuncSetAttribute(mma_gemm<DV, KV, 512, 0, 3, 3, 0, 0, 256, 0>,
                             cudaFuncAttributeMaxDynamicSharedMemorySize, SM3_256);
        cudaFuncSetAttribute(mma_gemm<DV, HV, 1536, 1, 1, 1, 1, HV, 256, 1>,
                             cudaFuncAttributeMaxDynamicSharedMemorySize, SM1_256);
        cudaFuncSetAttribute(mma_gemm<HV, INV, 1536, 1, 1, 2, 0, INV, 128, 0>,
                             cudaFuncAttributeMaxDynamicSharedMemorySize, SM1_128);
        attr_done = true;
    }

    // ---- prep ----
    {
        size_t n = (size_t)ROWS * INV;
        split_arr<<<(unsigned)((n + 255) / 256), 256>>>(mels, mh, ml, n);
    }
    prep_w<INV, HV, 256  ><<<(HV * 256  + 255) / 256, 256>>>(ew1, wh + OW1, wl + OW1);
    prep_w<HV,  DV, 1536 ><<<(DV * 1536 + 255) / 256, 256>>>(ew2, wh + OW2, wl + OW2);
    prep_w<DV,  HV, 1536 ><<<(HV * 1536 + 255) / 256, 256>>>(dw1, wh + OW3, wl + OW3);
    prep_w<HV,  INV, 1536><<<(INV * 1536 + 255) / 256, 256>>>(dw2, wh + OW4, wl + OW4);
    {
        size_t n = (size_t)KV * DV;
        split_arr<<<(unsigned)((n + 255) / 256), 256>>>(cb, cbh, cbl, n);
    }
    cnorm_init<<<KV / 8, 256>>>(cb, cn, keys);

    // ---- encoder (3-pass fp16 split == fp32-accurate) ----
    mma_gemm<INV, HV, 240, 1, 3, 0, 1, HV, 256, 0>
        <<<dim3(HV / 256, ROWS / 128), 256, SM3_256>>>(
        mh, ml, wh + OW1, wl + OW1, eb1, xh, xl, nullptr, nullptr, nullptr);
    mma_gemm<HV, DV, 1536, 1, 3, 0, 0, DV, 256, 0>
        <<<dim3(DV / 256, ROWS / 128), 256, SM3_256>>>(
        xh, xl, wh + OW2, wl + OW2, eb2, yh, yl, nullptr, nullptr, nullptr);

    // ---- VQ (3-pass split distances, exact argmin) ----
    mma_gemm<DV, KV, 512, 0, 3, 3, 0, 0, 256, 0>
        <<<dim3(KV / 256, ROWS / 128), 256, SM3_256>>>(
        yh, yl, cbh, cbl, cn, nullptr, nullptr, nullptr, keys, nullptr);
    idx_out<<<ROWS / 256, 256>>>(keys, idx_f);

    // ---- decoder (1-pass fp16; dec1 gathers codebook rows via keys) ----
    mma_gemm<DV, HV, 1536, 1, 1, 1, 1, HV, 256, 1>
        <<<dim3(HV / 256, ROWS / 128), 256, SM1_256>>>(
        cbh, nullptr, wh + OW3, nullptr, db1, yh, nullptr, nullptr, nullptr, keys);
    mma_gemm<HV, INV, 1536, 1, 1, 2, 0, INV, 128, 0>
        <<<dim3(1, ROWS / 128), 256, SM1_128>>>(
        yh, nullptr, wh + OW4, nullptr, db2, nullptr, nullptr, recon, nullptr, nullptr);
}